// round 1
// baseline (speedup 1.0000x reference)
#include <cuda_runtime.h>

#define TPB 256

// Computes cov = (R * diag-col-scale) @ (R * diag-col-scale)^T per point.
// scaling_raw: [N,3] fp32, rotation_raw: [N,4] fp32 (w,x,y,z), out: [N,3,3] fp32.
__global__ __launch_bounds__(TPB) void cov_kernel(
    const float* __restrict__ s_raw,
    const float4* __restrict__ q_raw,
    float* __restrict__ out,
    int n)
{
    __shared__ float sh_s[TPB * 3];   // staged scaling
    __shared__ float sh_o[TPB * 9];   // staged output

    const int full_blocks = n / TPB;
    const int block_base = blockIdx.x * TPB;

    if (blockIdx.x < full_blocks) {
        // ---- staged (vectorized) path: full block of TPB points ----
        // Load TPB*3 floats of scaling as float4s into shared.
        {
            const float4* g4 = reinterpret_cast<const float4*>(s_raw) +
                               (size_t)blockIdx.x * (TPB * 3 / 4);
            float4* s4 = reinterpret_cast<float4*>(sh_s);
            #pragma unroll
            for (int j = threadIdx.x; j < TPB * 3 / 4; j += TPB)
                s4[j] = g4[j];
        }
        __syncthreads();

        const int i = block_base + threadIdx.x;
        const float4 q = q_raw[i];
        const float n2 = q.x * q.x + q.y * q.y + q.z * q.z + q.w * q.w;
        const float inv = rsqrtf(fmaxf(n2, 1e-24f));
        const float w = q.x * inv, x = q.y * inv, y = q.z * inv, z = q.w * inv;

        const float sx = __expf(sh_s[threadIdx.x * 3 + 0]);
        const float sy = __expf(sh_s[threadIdx.x * 3 + 1]);
        const float sz = __expf(sh_s[threadIdx.x * 3 + 2]);

        // Rotation matrix rows, columns scaled by (sx, sy, sz)
        const float m00 = (1.f - 2.f * (y * y + z * z)) * sx;
        const float m01 = (2.f * (x * y - w * z)) * sy;
        const float m02 = (2.f * (x * z + w * y)) * sz;
        const float m10 = (2.f * (x * y + w * z)) * sx;
        const float m11 = (1.f - 2.f * (x * x + z * z)) * sy;
        const float m12 = (2.f * (y * z - w * x)) * sz;
        const float m20 = (2.f * (x * z - w * y)) * sx;
        const float m21 = (2.f * (y * z + w * x)) * sy;
        const float m22 = (1.f - 2.f * (x * x + y * y)) * sz;

        const float c00 = m00 * m00 + m01 * m01 + m02 * m02;
        const float c01 = m00 * m10 + m01 * m11 + m02 * m12;
        const float c02 = m00 * m20 + m01 * m21 + m02 * m22;
        const float c11 = m10 * m10 + m11 * m11 + m12 * m12;
        const float c12 = m10 * m20 + m11 * m21 + m12 * m22;
        const float c22 = m20 * m20 + m21 * m21 + m22 * m22;

        // Stride-9 smem writes: gcd(9,32)=1 -> conflict-free.
        float* o = &sh_o[threadIdx.x * 9];
        o[0] = c00; o[1] = c01; o[2] = c02;
        o[3] = c01; o[4] = c11; o[5] = c12;
        o[6] = c02; o[7] = c12; o[8] = c22;
        __syncthreads();

        // Stream out TPB*9 floats as float4s.
        {
            float4* g4 = reinterpret_cast<float4*>(out) +
                         (size_t)blockIdx.x * (TPB * 9 / 4);
            const float4* s4 = reinterpret_cast<const float4*>(sh_o);
            #pragma unroll
            for (int j = threadIdx.x; j < TPB * 9 / 4; j += TPB)
                g4[j] = s4[j];
        }
    } else {
        // ---- scalar tail path ----
        const int i = block_base + threadIdx.x;
        if (i >= n) return;
        const float4 q = q_raw[i];
        const float n2 = q.x * q.x + q.y * q.y + q.z * q.z + q.w * q.w;
        const float inv = rsqrtf(fmaxf(n2, 1e-24f));
        const float w = q.x * inv, x = q.y * inv, y = q.z * inv, z = q.w * inv;
        const float sx = __expf(s_raw[3 * (size_t)i + 0]);
        const float sy = __expf(s_raw[3 * (size_t)i + 1]);
        const float sz = __expf(s_raw[3 * (size_t)i + 2]);

        const float m00 = (1.f - 2.f * (y * y + z * z)) * sx;
        const float m01 = (2.f * (x * y - w * z)) * sy;
        const float m02 = (2.f * (x * z + w * y)) * sz;
        const float m10 = (2.f * (x * y + w * z)) * sx;
        const float m11 = (1.f - 2.f * (x * x + z * z)) * sy;
        const float m12 = (2.f * (y * z - w * x)) * sz;
        const float m20 = (2.f * (x * z - w * y)) * sx;
        const float m21 = (2.f * (y * z + w * x)) * sy;
        const float m22 = (1.f - 2.f * (x * x + y * y)) * sz;

        float* o = out + 9 * (size_t)i;
        o[0] = m00 * m00 + m01 * m01 + m02 * m02;
        o[1] = m00 * m10 + m01 * m11 + m02 * m12;
        o[2] = m00 * m20 + m01 * m21 + m02 * m22;
        o[3] = o[1];
        o[4] = m10 * m10 + m11 * m11 + m12 * m12;
        o[5] = m10 * m20 + m11 * m21 + m12 * m22;
        o[6] = o[2];
        o[7] = o[5];
        o[8] = m20 * m20 + m21 * m21 + m22 * m22;
    }
}

extern "C" void kernel_launch(void* const* d_in, const int* in_sizes, int n_in,
                              void* d_out, int out_size)
{
    const float*  s_raw = (const float*)d_in[0];          // [N,3]
    const float4* q_raw = (const float4*)d_in[1];         // [N,4]
    float*        out   = (float*)d_out;                  // [N,3,3]
    const int n = in_sizes[0] / 3;

    const int blocks = (n + TPB - 1) / TPB;
    cov_kernel<<<blocks, TPB>>>(s_raw, q_raw, out, n);
}